// round 11
// baseline (speedup 1.0000x reference)
#include <cuda_runtime.h>
#include <cstdint>

#define DEPTH    3
#define MARGIN   0.1f
#define BETA     0.5f
#define MAXN     16384          // max tokens (B*T); actual 2048
#define MAXWIDTH 262144         // max 2*V; actual 64000
#define TPB      256
#define FTPB     1024

// ---- device scratch (allocation-free; zero-initialized at module load;
//      g_hist restored to zero by final_kernel every invocation) ----
// The count-min sketch is algebraically degenerate: salts are a common
// shift per depth, so min over depths == multiplicity of (combined % width).
// One histogram row suffices; salts never reach device code.
__device__ int   g_hist[MAXWIDTH];
__device__ int   g_cm  [MAXN];       // combined % width per token
__device__ float g_row_nll [MAXN];   // masked log(p_target)
__device__ float g_row_mask[MAXN];   // valid flag
__device__ float g_row_rerr[MAXN];   // max(p_idk - p_target + MARGIN, 0)

// fast softplus for the bulk sum (MUFU EX2/LG2 path)
__device__ __forceinline__ float softplus_fast(float x) {
    float e = __expf(-fabsf(x));
    return fmaxf(x, 0.0f) + __logf(1.0f + e);
}
// precise softplus for the two per-row scalars feeding log()
__device__ __forceinline__ float softplus_precise(float x) {
    float e = expf(-fabsf(x));
    return fmaxf(x, 0.0f) + log1pf(e);
}

// ---------------- kernel 1: pure streaming, one block per row ------------
// The only pass over the big tensor. No hash duty, no elections, no fences
// (R4/R8/R9: any per-block end-of-kernel gpu-scope atomic costs ~20us).
__global__ void __launch_bounds__(TPB) row_kernel(const float* __restrict__ logits,
                                                  const long long* __restrict__ targets,
                                                  int V, int vec_ok) {
    const int r   = blockIdx.x;
    const int tid = threadIdx.x;
    const float* row = logits + (size_t)r * V;

    float acc = 0.0f;
    if (vec_ok) {
        const float4* row4 = reinterpret_cast<const float4*>(row);
        const int n4 = V >> 2;
#pragma unroll 4
        for (int i = tid; i < n4; i += TPB) {
            float4 v = __ldcs(&row4[i]);   // single-use stream: evict-first
            acc += softplus_fast(v.x);
            acc += softplus_fast(v.y);
            acc += softplus_fast(v.z);
            acc += softplus_fast(v.w);
        }
    } else {
        for (int i = tid; i < V; i += TPB)
            acc += softplus_fast(row[i]);
    }

    __shared__ float warp_sums[TPB / 32];
#pragma unroll
    for (int off = 16; off > 0; off >>= 1)
        acc += __shfl_xor_sync(0xFFFFFFFFu, acc, off);
    int lane = tid & 31, wid = tid >> 5;
    if (lane == 0) warp_sums[wid] = acc;
    __syncthreads();

    if (tid == 0) {
        float S = 0.0f;
#pragma unroll
        for (int w = 0; w < TPB / 32; w++) S += warp_sums[w];

        long long t = targets[r];
        bool valid  = (t != -1);
        int ti = (t >= 0 && t < V) ? (int)t : 0;
        float spt = softplus_precise(row[ti]);
        float spi = softplus_precise(row[0]);

        float scale = fminf(1.0f / (S + 1e-6f), 1.0f);
        float rem   = fmaxf(1.0f - S * scale, 0.0f);
        float p_t   = spt * scale + ((t == 0) ? rem : 0.0f);
        float p_i   = spi * scale + rem;

        g_row_nll [r] = valid ? logf(fmaxf(p_t, 1e-10f)) : 0.0f;
        g_row_mask[r] = valid ? 1.0f : 0.0f;
        g_row_rerr[r] = fmaxf(p_i - p_t + MARGIN, 0.0f);
    }
}

// ---------------- kernel 2: hash (pre-sync) + query + reduce (PDL) -------
// With programmatic stream serialization this kernel begins executing while
// row_kernel is still streaming. Phase A (hashing) depends only on
// inputs/targets, so it runs entirely inside the overlap window — free.
// Phase B runs after cudaGridDependencySynchronize().
__global__ void __launch_bounds__(FTPB) final_kernel(const long long* __restrict__ targets,
                                                     const long long* __restrict__ inputs,
                                                     float* __restrict__ out,
                                                     int N, int V) {
    const int tid = threadIdx.x;

    // ---- phase A: token hashing + histogram build (overlapped) ----
    long long width = 2LL * V;
    for (int n = tid; n < N; n += FTPB) {
        long long combined = inputs[n] * 31337LL + targets[n] * 2654435769LL;
        long long cm = combined % width;
        if (cm < 0) cm += width;
        int cmi = (int)cm;
        g_cm[n] = cmi;
        atomicAdd(&g_hist[cmi], 1);
    }
    __syncthreads();   // histogram complete for this (only) block

    // ---- wait for row_kernel's results ----
#if __CUDA_ARCH__ >= 900
    cudaGridDependencySynchronize();
#endif

    // ---- phase B: query + deterministic reduction ----
    float nll_sum = 0.0f, mask_sum = 0.0f, basis_sum = 0.0f;

    for (int base = 0; base < N; base += FTPB * 2) {
        int   cm[2];
        float rr[2];
#pragma unroll
        for (int k = 0; k < 2; k++) {
            int n = base + k * FTPB + tid;
            if (n < N) {
                nll_sum  += g_row_nll[n];
                mask_sum += g_row_mask[n];
                rr[k]     = g_row_rerr[n];
                cm[k]     = g_cm[n];
            }
        }
#pragma unroll
        for (int k = 0; k < 2; k++) {
            int n = base + k * FTPB + tid;
            if (n < N) {
                int c = __ldcg(&g_hist[cm[k]]);
                basis_sum += rr[k] * tanhf((float)c * 0.1f);
            }
        }
    }

    __syncthreads();   // all queries done before any restore decrements

    // restore histogram to zero by replaying hashes (graph-replay safe)
    for (int n = tid; n < N; n += FTPB)
        atomicSub(&g_hist[g_cm[n]], 1);

    // deterministic fixed-order reduction
    __shared__ float s0[32], s1[32], s2[32];
#pragma unroll
    for (int off = 16; off > 0; off >>= 1) {
        nll_sum   += __shfl_xor_sync(0xFFFFFFFFu, nll_sum,   off);
        mask_sum  += __shfl_xor_sync(0xFFFFFFFFu, mask_sum,  off);
        basis_sum += __shfl_xor_sync(0xFFFFFFFFu, basis_sum, off);
    }
    int lane = tid & 31, wid = tid >> 5;
    if (lane == 0) { s0[wid] = nll_sum; s1[wid] = mask_sum; s2[wid] = basis_sum; }
    __syncthreads();
    if (tid == 0) {
        float a = 0, b = 0, c = 0;
#pragma unroll
        for (int w = 0; w < 32; w++) { a += s0[w]; b += s1[w]; c += s2[w]; }
        out[0] = -a / fmaxf(b, 1.0f) + BETA * (c / (float)N);
    }
}

extern "C" void kernel_launch(void* const* d_in, const int* in_sizes, int n_in,
                              void* d_out, int out_size) {
    // Resolve pointers by element count (robust to metadata ordering):
    //   salts: size == DEPTH (unused — algebraically eliminated);
    //   logits: largest; targets then inputs (relative order).
    const float*     logits  = nullptr;
    const long long* tok[2]  = {nullptr, nullptr};
    int ntok_arrays = 0;
    long long logits_size = 0;
    int N = 0;

    for (int i = 0; i < n_in; i++) {
        long long sz = in_sizes[i];
        if (sz == DEPTH) {
            // salts — common per-depth shift cancels in the min
        } else if (sz > 1000000) {
            logits = (const float*)d_in[i];
            logits_size = sz;
        } else {
            if (ntok_arrays < 2) tok[ntok_arrays] = (const long long*)d_in[i];
            ntok_arrays++;
            N = (int)sz;
        }
    }
    const long long* targets = tok[0];
    const long long* inputs  = tok[1];

    int V = (N > 0) ? (int)(logits_size / N) : 0;
    float* out = (float*)d_out;

    int vec_ok = (((uintptr_t)logits & 15) == 0) && (V % 4 == 0);

    row_kernel<<<N, TPB>>>(logits, targets, V, vec_ok);

    // PDL launch: final_kernel starts while row_kernel streams; its phase A
    // (hashing) is thereby hidden entirely.
    cudaLaunchAttribute attrs[1];
    attrs[0].id = cudaLaunchAttributeProgrammaticStreamSerialization;
    attrs[0].val.programmaticStreamSerializationAllowed = 1;
    cudaLaunchConfig_t cfg = {};
    cfg.gridDim  = dim3(1, 1, 1);
    cfg.blockDim = dim3(FTPB, 1, 1);
    cfg.dynamicSmemBytes = 0;
    cfg.stream = 0;
    cfg.attrs = attrs;
    cfg.numAttrs = 1;
    cudaLaunchKernelEx(&cfg, final_kernel, targets, inputs, out, N, V);
}

// round 12
// speedup vs baseline: 1.0245x; 1.0245x over previous
#include <cuda_runtime.h>
#include <cstdint>

#define DEPTH    3
#define MARGIN   0.1f
#define BETA     0.5f
#define MAXN     16384          // max tokens (B*T); actual 2048
#define MAXWIDTH 262144         // max 2*V; actual 64000
#define TPB      256
#define FTPB     1024
#define KMAX     (MAXN / FTPB)  // max tokens per final-kernel thread (16)

// ---- device scratch (allocation-free; zero-initialized at module load;
//      g_hist restored to zero by final_kernel every invocation) ----
// The count-min sketch is algebraically degenerate: salts are a common
// shift per depth, so min over depths == multiplicity of (combined % width).
// One histogram row suffices; salts never reach device code.
__device__ int   g_hist[MAXWIDTH];
__device__ float g_row_nll [MAXN];   // masked log(p_target)
__device__ float g_row_mask[MAXN];   // valid flag
__device__ float g_row_rerr[MAXN];   // max(p_idk - p_target + MARGIN, 0)

// fast softplus for the bulk sum (MUFU EX2/LG2 path)
__device__ __forceinline__ float softplus_fast(float x) {
    float e = __expf(-fabsf(x));
    return fmaxf(x, 0.0f) + __logf(1.0f + e);
}
// precise softplus for the two per-row scalars feeding log()
__device__ __forceinline__ float softplus_precise(float x) {
    float e = expf(-fabsf(x));
    return fmaxf(x, 0.0f) + log1pf(e);
}

// PDL controls (inline PTX; header intrinsics gated awkwardly by arch)
__device__ __forceinline__ void pdl_trigger() {
#if __CUDA_ARCH__ >= 900
    asm volatile("griddepcontrol.launch_dependents;");
#endif
}
__device__ __forceinline__ void pdl_wait() {
#if __CUDA_ARCH__ >= 900
    asm volatile("griddepcontrol.wait;");
#endif
}

// ---------------- kernel 1: pure streaming, one block per row ------------
// The only pass over the big tensor. No hash duty, no elections, no fences
// (R4/R8/R9: any per-block end-of-kernel gpu-scope atomic costs ~20us).
// Early PDL trigger: once every block has started, the dependent final
// kernel launches and runs its hash phase under the stream's tail.
__global__ void __launch_bounds__(TPB) row_kernel(const float* __restrict__ logits,
                                                  const long long* __restrict__ targets,
                                                  int V, int vec_ok) {
    pdl_trigger();

    const int r   = blockIdx.x;
    const int tid = threadIdx.x;
    const float* row = logits + (size_t)r * V;

    float acc = 0.0f;
    if (vec_ok) {
        const float4* row4 = reinterpret_cast<const float4*>(row);
        const int n4 = V >> 2;
#pragma unroll 4
        for (int i = tid; i < n4; i += TPB) {
            float4 v = __ldcs(&row4[i]);   // single-use stream: evict-first
            acc += softplus_fast(v.x);
            acc += softplus_fast(v.y);
            acc += softplus_fast(v.z);
            acc += softplus_fast(v.w);
        }
    } else {
        for (int i = tid; i < V; i += TPB)
            acc += softplus_fast(row[i]);
    }

    __shared__ float warp_sums[TPB / 32];
#pragma unroll
    for (int off = 16; off > 0; off >>= 1)
        acc += __shfl_xor_sync(0xFFFFFFFFu, acc, off);
    int lane = tid & 31, wid = tid >> 5;
    if (lane == 0) warp_sums[wid] = acc;
    __syncthreads();

    if (tid == 0) {
        float S = 0.0f;
#pragma unroll
        for (int w = 0; w < TPB / 32; w++) S += warp_sums[w];

        long long t = targets[r];
        bool valid  = (t != -1);
        int ti = (t >= 0 && t < V) ? (int)t : 0;
        float spt = softplus_precise(row[ti]);
        float spi = softplus_precise(row[0]);

        float scale = fminf(1.0f / (S + 1e-6f), 1.0f);
        float rem   = fmaxf(1.0f - S * scale, 0.0f);
        float p_t   = spt * scale + ((t == 0) ? rem : 0.0f);
        float p_i   = spi * scale + rem;

        g_row_nll [r] = valid ? logf(fmaxf(p_t, 1e-10f)) : 0.0f;
        g_row_mask[r] = valid ? 1.0f : 0.0f;
        g_row_rerr[r] = fmaxf(p_i - p_t + MARGIN, 0.0f);
    }
}

// ---------------- kernel 2: hash (overlapped) + query + reduce (PDL) -----
// Launches early via the primary's trigger. Phase A (hashing) runs while
// row_kernel still streams; bucket indices stay in REGISTERS across the
// grid-dependency wait, so phase B needs no g_cm reload and the restore is
// plain zero-stores. Phase B is the only serialized tail.
__global__ void __launch_bounds__(FTPB) final_kernel(const long long* __restrict__ targets,
                                                     const long long* __restrict__ inputs,
                                                     float* __restrict__ out,
                                                     int N, int V) {
    const int tid = threadIdx.x;
    const long long width = 2LL * V;

    // ---- phase A: token hashing + histogram build (overlapped) ----
    int cm[KMAX];
#pragma unroll
    for (int k = 0; k < KMAX; k++) {
        int n = k * FTPB + tid;
        if (n < N) {
            long long combined = inputs[n] * 31337LL + targets[n] * 2654435769LL;
            long long c = combined % width;
            if (c < 0) c += width;
            cm[k] = (int)c;
            atomicAdd(&g_hist[cm[k]], 1);
        }
    }
    __syncthreads();   // histogram complete (single block)

    // ---- wait for row_kernel's results ----
    pdl_wait();

    // ---- phase B: query + deterministic reduction ----
    float nll_sum = 0.0f, mask_sum = 0.0f, basis_sum = 0.0f;
    float rr[KMAX];

#pragma unroll
    for (int k = 0; k < KMAX; k++) {          // independent load wave
        int n = k * FTPB + tid;
        if (n < N) {
            nll_sum  += g_row_nll[n];
            mask_sum += g_row_mask[n];
            rr[k]     = g_row_rerr[n];
        }
    }
#pragma unroll
    for (int k = 0; k < KMAX; k++) {          // dependent gather wave
        int n = k * FTPB + tid;
        if (n < N) {
            int c = __ldcg(&g_hist[cm[k]]);
            basis_sum += rr[k] * tanhf((float)c * 0.1f);
        }
    }

    __syncthreads();   // all queries done before any restore store

    // restore histogram to zero: plain stores (duplicates all write 0)
#pragma unroll
    for (int k = 0; k < KMAX; k++) {
        int n = k * FTPB + tid;
        if (n < N) g_hist[cm[k]] = 0;
    }

    // deterministic fixed-order reduction
    __shared__ float s0[32], s1[32], s2[32];
#pragma unroll
    for (int off = 16; off > 0; off >>= 1) {
        nll_sum   += __shfl_xor_sync(0xFFFFFFFFu, nll_sum,   off);
        mask_sum  += __shfl_xor_sync(0xFFFFFFFFu, mask_sum,  off);
        basis_sum += __shfl_xor_sync(0xFFFFFFFFu, basis_sum, off);
    }
    int lane = tid & 31, wid = tid >> 5;
    if (lane == 0) { s0[wid] = nll_sum; s1[wid] = mask_sum; s2[wid] = basis_sum; }
    __syncthreads();
    if (tid == 0) {
        float a = 0, b = 0, c = 0;
#pragma unroll
        for (int w = 0; w < 32; w++) { a += s0[w]; b += s1[w]; c += s2[w]; }
        out[0] = -a / fmaxf(b, 1.0f) + BETA * (c / (float)N);
    }
}

extern "C" void kernel_launch(void* const* d_in, const int* in_sizes, int n_in,
                              void* d_out, int out_size) {
    // Resolve pointers by element count (robust to metadata ordering):
    //   salts: size == DEPTH (unused — algebraically eliminated);
    //   logits: largest; targets then inputs (relative order).
    const float*     logits  = nullptr;
    const long long* tok[2]  = {nullptr, nullptr};
    int ntok_arrays = 0;
    long long logits_size = 0;
    int N = 0;

    for (int i = 0; i < n_in; i++) {
        long long sz = in_sizes[i];
        if (sz == DEPTH) {
            // salts — common per-depth shift cancels in the min
        } else if (sz > 1000000) {
            logits = (const float*)d_in[i];
            logits_size = sz;
        } else {
            if (ntok_arrays < 2) tok[ntok_arrays] = (const long long*)d_in[i];
            ntok_arrays++;
            N = (int)sz;
        }
    }
    const long long* targets = tok[0];
    const long long* inputs  = tok[1];

    int V = (N > 0) ? (int)(logits_size / N) : 0;
    float* out = (float*)d_out;

    int vec_ok = (((uintptr_t)logits & 15) == 0) && (V % 4 == 0);

    row_kernel<<<N, TPB>>>(logits, targets, V, vec_ok);

    // PDL launch: with the primary's explicit trigger, this kernel starts
    // while row_kernel streams; phase A (hashing) is hidden entirely.
    cudaLaunchAttribute attrs[1];
    attrs[0].id = cudaLaunchAttributeProgrammaticStreamSerialization;
    attrs[0].val.programmaticStreamSerializationAllowed = 1;
    cudaLaunchConfig_t cfg = {};
    cfg.gridDim  = dim3(1, 1, 1);
    cfg.blockDim = dim3(FTPB, 1, 1);
    cfg.dynamicSmemBytes = 0;
    cfg.stream = 0;
    cfg.attrs = attrs;
    cfg.numAttrs = 1;
    cudaLaunchKernelEx(&cfg, final_kernel, targets, inputs, out, N, V);
}

// round 13
// speedup vs baseline: 1.0332x; 1.0085x over previous
#include <cuda_runtime.h>
#include <cstdint>

#define DEPTH    3
#define MARGIN   0.1f
#define BETA     0.5f
#define MAXN     16384          // max tokens (B*T); actual 2048
#define MAXWIDTH 262144         // max 2*V; actual 64000
#define TPB      128            // 4 warps/block -> all 2048 blocks co-resident (1 wave)
#define FTPB     1024
#define KREG     4              // register-resident tokens/thread (covers N <= 4096)

// ---- device scratch (allocation-free; zero-initialized at module load;
//      g_hist restored to zero by final_kernel every invocation) ----
// The count-min sketch is algebraically degenerate: salts are a common
// shift per depth, so min over depths == multiplicity of (combined % width).
// One histogram row suffices; salts never reach device code.
__device__ int   g_hist[MAXWIDTH];
__device__ float g_row_nll [MAXN];   // masked log(p_target)
__device__ float g_row_mask[MAXN];   // valid flag
__device__ float g_row_rerr[MAXN];   // max(p_idk - p_target + MARGIN, 0)

// fast softplus for the bulk sum (MUFU EX2/LG2 path)
__device__ __forceinline__ float softplus_fast(float x) {
    float e = __expf(-fabsf(x));
    return fmaxf(x, 0.0f) + __logf(1.0f + e);
}
// precise softplus for the two per-row scalars feeding log()
__device__ __forceinline__ float softplus_precise(float x) {
    float e = expf(-fabsf(x));
    return fmaxf(x, 0.0f) + log1pf(e);
}
// fast tanh for x >= 0: 1 - 2/(e^{2x}+1)   (one MUFU exp + one rcp)
__device__ __forceinline__ float tanh_pos(float x) {
    return 1.0f - 2.0f * __frcp_rn(__expf(2.0f * x) + 1.0f);
}

// PDL controls
__device__ __forceinline__ void pdl_trigger() {
#if __CUDA_ARCH__ >= 900
    asm volatile("griddepcontrol.launch_dependents;");
#endif
}
__device__ __forceinline__ void pdl_wait() {
#if __CUDA_ARCH__ >= 900
    asm volatile("griddepcontrol.wait;");
#endif
}

__device__ __forceinline__ int token_bucket(const long long* inputs,
                                            const long long* targets,
                                            int n, long long width) {
    long long combined = inputs[n] * 31337LL + targets[n] * 2654435769LL;
    long long c = combined % width;
    if (c < 0) c += width;
    return (int)c;
}

// ---------------- kernel 1: pure streaming, one block per row ------------
// The only pass over the big tensor. 128 threads/block so the entire grid is
// one resident wave (no wave transition, no underfilled second wave).
// No elections/fences (R4/R8/R9: per-block gpu-scope atomics cost ~20us).
__global__ void __launch_bounds__(TPB) row_kernel(const float* __restrict__ logits,
                                                  const long long* __restrict__ targets,
                                                  int V, int vec_ok) {
    pdl_trigger();

    const int r   = blockIdx.x;
    const int tid = threadIdx.x;
    const float* row = logits + (size_t)r * V;

    float acc = 0.0f;
    if (vec_ok) {
        const float4* row4 = reinterpret_cast<const float4*>(row);
        const int n4 = V >> 2;
#pragma unroll 4
        for (int i = tid; i < n4; i += TPB) {
            float4 v = __ldcs(&row4[i]);   // single-use stream: evict-first
            acc += softplus_fast(v.x);
            acc += softplus_fast(v.y);
            acc += softplus_fast(v.z);
            acc += softplus_fast(v.w);
        }
    } else {
        for (int i = tid; i < V; i += TPB)
            acc += softplus_fast(row[i]);
    }

    __shared__ float warp_sums[TPB / 32];
#pragma unroll
    for (int off = 16; off > 0; off >>= 1)
        acc += __shfl_xor_sync(0xFFFFFFFFu, acc, off);
    int lane = tid & 31, wid = tid >> 5;
    if (lane == 0) warp_sums[wid] = acc;
    __syncthreads();

    if (tid == 0) {
        float S = 0.0f;
#pragma unroll
        for (int w = 0; w < TPB / 32; w++) S += warp_sums[w];

        long long t = targets[r];
        bool valid  = (t != -1);
        int ti = (t >= 0 && t < V) ? (int)t : 0;
        float spt = softplus_precise(row[ti]);
        float spi = softplus_precise(row[0]);

        float scale = fminf(1.0f / (S + 1e-6f), 1.0f);
        float rem   = fmaxf(1.0f - S * scale, 0.0f);
        float p_t   = spt * scale + ((t == 0) ? rem : 0.0f);
        float p_i   = spi * scale + rem;

        g_row_nll [r] = valid ? logf(fmaxf(p_t, 1e-10f)) : 0.0f;
        g_row_mask[r] = valid ? 1.0f : 0.0f;
        g_row_rerr[r] = fmaxf(p_i - p_t + MARGIN, 0.0f);
    }
}

// ---------------- kernel 2: hash (overlapped) + query + reduce (PDL) -----
// Starts early via the primary's trigger; phase A (hashing) executes while
// row_kernel streams. Bucket indices for the first KREG*FTPB tokens stay in
// registers across the wait; larger N falls back to recomputation.
__global__ void __launch_bounds__(FTPB) final_kernel(const long long* __restrict__ targets,
                                                     const long long* __restrict__ inputs,
                                                     float* __restrict__ out,
                                                     int N, int V) {
    const int tid = threadIdx.x;
    const long long width = 2LL * V;

    // ---- phase A: token hashing + histogram build (overlapped) ----
    int cm[KREG];
#pragma unroll
    for (int k = 0; k < KREG; k++) {
        int n = k * FTPB + tid;
        cm[k] = (n < N) ? token_bucket(inputs, targets, n, width) : 0;
        if (n < N) atomicAdd(&g_hist[cm[k]], 1);
    }
    for (int n = KREG * FTPB + tid; n < N; n += FTPB)       // fallback (N > 4096)
        atomicAdd(&g_hist[token_bucket(inputs, targets, n, width)], 1);
    __syncthreads();   // histogram complete (single block)

    // ---- wait for row_kernel's results ----
    pdl_wait();

    // ---- phase B: query + deterministic reduction ----
    float nll_sum = 0.0f, mask_sum = 0.0f, basis_sum = 0.0f;
    float rr[KREG];

#pragma unroll
    for (int k = 0; k < KREG; k++) {          // independent load wave
        int n = k * FTPB + tid;
        if (n < N) {
            nll_sum  += g_row_nll[n];
            mask_sum += g_row_mask[n];
            rr[k]     = g_row_rerr[n];
        }
    }
#pragma unroll
    for (int k = 0; k < KREG; k++) {          // dependent gather wave
        int n = k * FTPB + tid;
        if (n < N) {
            int c = __ldcg(&g_hist[cm[k]]);
            basis_sum += rr[k] * tanh_pos((float)c * 0.1f);
        }
    }
    for (int n = KREG * FTPB + tid; n < N; n += FTPB) {     // fallback (N > 4096)
        nll_sum  += g_row_nll[n];
        mask_sum += g_row_mask[n];
        int c = __ldcg(&g_hist[token_bucket(inputs, targets, n, width)]);
        basis_sum += g_row_rerr[n] * tanh_pos((float)c * 0.1f);
    }

    __syncthreads();   // all queries done before any restore store

    // restore histogram to zero: plain stores (duplicates all write 0)
#pragma unroll
    for (int k = 0; k < KREG; k++) {
        int n = k * FTPB + tid;
        if (n < N) g_hist[cm[k]] = 0;
    }
    for (int n = KREG * FTPB + tid; n < N; n += FTPB)       // fallback (N > 4096)
        g_hist[token_bucket(inputs, targets, n, width)] = 0;

    // deterministic fixed-order reduction
    __shared__ float s0[32], s1[32], s2[32];
#pragma unroll
    for (int off = 16; off > 0; off >>= 1) {
        nll_sum   += __shfl_xor_sync(0xFFFFFFFFu, nll_sum,   off);
        mask_sum  += __shfl_xor_sync(0xFFFFFFFFu, mask_sum,  off);
        basis_sum += __shfl_xor_sync(0xFFFFFFFFu, basis_sum, off);
    }
    int lane = tid & 31, wid = tid >> 5;
    if (lane == 0) { s0[wid] = nll_sum; s1[wid] = mask_sum; s2[wid] = basis_sum; }
    __syncthreads();
    if (tid == 0) {
        float a = 0, b = 0, c = 0;
#pragma unroll
        for (int w = 0; w < 32; w++) { a += s0[w]; b += s1[w]; c += s2[w]; }
        out[0] = -a / fmaxf(b, 1.0f) + BETA * (c / (float)N);
    }
}

extern "C" void kernel_launch(void* const* d_in, const int* in_sizes, int n_in,
                              void* d_out, int out_size) {
    // Resolve pointers by element count (robust to metadata ordering):
    //   salts: size == DEPTH (unused — algebraically eliminated);
    //   logits: largest; targets then inputs (relative order).
    const float*     logits  = nullptr;
    const long long* tok[2]  = {nullptr, nullptr};
    int ntok_arrays = 0;
    long long logits_size = 0;
    int N = 0;

    for (int i = 0; i < n_in; i++) {
        long long sz = in_sizes[i];
        if (sz == DEPTH) {
            // salts — common per-depth shift cancels in the min
        } else if (sz > 1000000) {
            logits = (const float*)d_in[i];
            logits_size = sz;
        } else {
            if (ntok_arrays < 2) tok[ntok_arrays] = (const long long*)d_in[i];
            ntok_arrays++;
            N = (int)sz;
        }
    }
    const long long* targets = tok[0];
    const long long* inputs  = tok[1];

    int V = (N > 0) ? (int)(logits_size / N) : 0;
    float* out = (float*)d_out;

    int vec_ok = (((uintptr_t)logits & 15) == 0) && (V % 4 == 0);

    row_kernel<<<N, TPB>>>(logits, targets, V, vec_ok);

    // PDL launch: with the primary's explicit trigger, this kernel starts
    // while row_kernel streams; phase A (hashing) is hidden entirely.
    cudaLaunchAttribute attrs[1];
    attrs[0].id = cudaLaunchAttributeProgrammaticStreamSerialization;
    attrs[0].val.programmaticStreamSerializationAllowed = 1;
    cudaLaunchConfig_t cfg = {};
    cfg.gridDim  = dim3(1, 1, 1);
    cfg.blockDim = dim3(FTPB, 1, 1);
    cfg.dynamicSmemBytes = 0;
    cfg.stream = 0;
    cfg.attrs = attrs;
    cfg.numAttrs = 1;
    cudaLaunchKernelEx(&cfg, final_kernel, targets, inputs, out, N, V);
}